// round 12
// baseline (speedup 1.0000x reference)
#include <cuda_runtime.h>
#include <cuda_bf16.h>
#include <cuda_fp16.h>
#include <cstdint>
#include <math.h>

#define B_   4
#define LQ_  1024
#define LKV_ 4096
#define D_   512
#define H_   4
#define HD_  128
#define SCALE_ 0.08838834764831845f      // 1/sqrt(128)
#define LOG2E_ 1.4426950408889634f
#define QSCALE_ (SCALE_ * LOG2E_)        // logits emitted in log2 domain

// ---------------------------------------------------------------------------
// Helpers
// ---------------------------------------------------------------------------
__device__ __forceinline__ uint32_t smem_u32(const void* p) {
    uint32_t a;
    asm("{ .reg .u64 t; cvta.to.shared.u64 t, %1; cvt.u32.u64 %0, t; }" : "=r"(a) : "l"(p));
    return a;
}

#define CP_ASYNC16(sa, g) \
    asm volatile("cp.async.cg.shared.global [%0], [%1], 16;" :: "r"(sa), "l"(g))
#define CP_COMMIT() asm volatile("cp.async.commit_group;" ::: "memory")
#define CP_WAIT(n)  asm volatile("cp.async.wait_group %0;" :: "n"(n) : "memory")

__device__ __forceinline__ void ldsm4(uint32_t* r, uint32_t a) {
    asm volatile("ldmatrix.sync.aligned.m8n8.x4.shared.b16 {%0,%1,%2,%3}, [%4];"
                 : "=r"(r[0]), "=r"(r[1]), "=r"(r[2]), "=r"(r[3]) : "r"(a));
}
__device__ __forceinline__ void mma_f16(float* c, const uint32_t* a, const uint32_t* b) {
    asm volatile("mma.sync.aligned.m16n8k16.row.col.f32.f16.f16.f32 "
                 "{%0,%1,%2,%3}, {%4,%5,%6,%7}, {%8,%9}, {%0,%1,%2,%3};"
                 : "+f"(c[0]), "+f"(c[1]), "+f"(c[2]), "+f"(c[3])
                 : "r"(a[0]), "r"(a[1]), "r"(a[2]), "r"(a[3]), "r"(b[0]), "r"(b[1]));
}
__device__ __forceinline__ uint32_t pack_h2(float a, float b) {
    __half2 v = __floats2half2_rn(a, b);
    return *(uint32_t*)&v;
}

// 128B-row swizzle (8 granules of 16B per row), conflict-free for ldsm
#define SWR(r, g) ((uint32_t)(r) * 128 + ((uint32_t)((g) ^ ((r) & 7)) << 4))
// 256B-row swizzle (flash Q/K tiles)
#define SWQ(r, g) ((uint32_t)(r) * 256 + ((uint32_t)((g) ^ ((r) & 15)) << 4))

// ---------------------------------------------------------------------------
// Device scratch (allocation-free)
// ---------------------------------------------------------------------------
#define NX  ((size_t)B_ * LQ_ * D_)
#define NE  ((size_t)B_ * LKV_ * D_)
#define NW  ((size_t)D_ * D_)

__device__ __half g_xh[NX];
__device__ __half g_eh[NE];
__device__ __half g_wqhi[NW], g_wqlo[NW];
__device__ __half g_wk[NW];
__device__ __half g_wv[NW];
__device__ __half g_wohi[NW], g_wolo[NW];
__device__ __half g_qh[NX];
__device__ __half g_kh[NE];
__device__ __half g_vth[NE];           // transposed [b][h*HD+d][lkv]
__device__ __half g_ct[NX];

// ---------------------------------------------------------------------------
// Single prep kernel: y selects task
// ---------------------------------------------------------------------------
__global__ __launch_bounds__(256) void prep_kernel(
    const float* __restrict__ x, const float* __restrict__ enc,
    const float* __restrict__ Wq, const float* __restrict__ Wk,
    const float* __restrict__ Wv, const float* __restrict__ Wo,
    __half* __restrict__ xh, __half* __restrict__ eh,
    __half* __restrict__ wqh, __half* __restrict__ wql,
    __half* __restrict__ wk, __half* __restrict__ wv,
    __half* __restrict__ woh, __half* __restrict__ wol)
{
    const int which = blockIdx.y;
    const int stride = gridDim.x * blockDim.x;
    const int tid0 = blockIdx.x * blockDim.x + threadIdx.x;
    if (which <= 1 || which == 3 || which == 4) {
        const float* in = (which == 0) ? x : (which == 1) ? enc : (which == 3) ? Wk : Wv;
        __half* outp    = (which == 0) ? xh : (which == 1) ? eh : (which == 3) ? wk : wv;
        const int n4    = (which == 0) ? (int)(NX / 4) : (which == 1) ? (int)(NE / 4) : (int)(NW / 4);
        for (int i = tid0; i < n4; i += stride) {
            float4 v = ((const float4*)in)[i];
            ((uint2*)outp)[i] = make_uint2(pack_h2(v.x, v.y), pack_h2(v.z, v.w));
        }
    } else {
        const float* in = (which == 2) ? Wq : Wo;
        __half* hi = (which == 2) ? wqh : woh;
        __half* lo = (which == 2) ? wql : wol;
        const int n4 = (int)(NW / 4);
        for (int i = tid0; i < n4; i += stride) {
            float4 v = ((const float4*)in)[i];
            float f[4] = {v.x, v.y, v.z, v.w};
            float h[4], l[4];
#pragma unroll
            for (int j = 0; j < 4; j++) {
                h[j] = __half2float(__float2half_rn(f[j]));
                l[j] = f[j] - h[j];
            }
            ((uint2*)hi)[i] = make_uint2(pack_h2(h[0], h[1]), pack_h2(h[2], h[3]));
            ((uint2*)lo)[i] = make_uint2(pack_h2(l[0], l[1]), pack_h2(l[2], l[3]));
        }
    }
}

// ---------------------------------------------------------------------------
// Merged QKV projection kernel. z: 0=K (1-pass), 1=V transposed (1-pass),
// 2=Q (2-pass hi/lo, pre-scaled). K-chunk 64. CTA tile 128x128.
// 1-pass: 3-stage ring, no trailing barrier. 2-pass: 2-stage, both barriers.
// ---------------------------------------------------------------------------
#define OFF_A  0
#define OFF_BH 16384
#define OFF_BL 32768
#define GEMM_SMEM 98304

__global__ __launch_bounds__(256) void qkv_kernel(
    const __half* __restrict__ xh, const __half* __restrict__ eh,
    const __half* __restrict__ wqh, const __half* __restrict__ wql,
    const __half* __restrict__ wk, const __half* __restrict__ wv,
    __half* __restrict__ qh, __half* __restrict__ kh, __half* __restrict__ vth,
    const float* __restrict__ bq, const float* __restrict__ bk,
    const float* __restrict__ bv)
{
    const int zz = blockIdx.z;
    if (zz == 2 && blockIdx.y >= 32) return;

    extern __shared__ char smem[];
    const uint32_t sb = smem_u32(smem);
    const int t = threadIdx.x, wid = t >> 5, lid = t & 31;
    const int wm = wid & 1, wn = wid >> 1;
    const int m0 = blockIdx.y * 128, n0 = blockIdx.x * 128;

    const bool twop = (zz == 2);
    const int STG = twop ? 49152 : 32768;
    const int NSTAGE = twop ? 2 : 3;

    const __half* A    = twop ? xh : eh;
    const __half* Bsel = (zz == 0) ? wk : (zz == 1) ? wv : wqh;
    const float* bsel  = (zz == 0) ? bk : (zz == 1) ? bv : bq;
    const float scale  = twop ? QSCALE_ : 1.0f;

    const __half* Ab  = A + (size_t)m0 * D_;
    const __half* Bbh = Bsel + (size_t)n0 * D_;
    const __half* Bbl = twop ? (wql + (size_t)n0 * D_) : nullptr;

    float acc[4][4][4];
#pragma unroll
    for (int i = 0; i < 4; i++)
#pragma unroll
        for (int j = 0; j < 4; j++)
#pragma unroll
            for (int r = 0; r < 4; r++) acc[i][j][r] = 0.f;

    const int nch = D_ >> 6;   // 8 chunks of 64

    auto load_stage = [&](int c) {
        const int k0 = c << 6;
        const uint32_t sbase = sb + (c % NSTAGE) * STG;
#pragma unroll
        for (int i = 0; i < 4; i++) {
            int idx = t + i * 256;
            int r = idx >> 3, s = idx & 7;
            uint32_t so = SWR(r, s);
            size_t oa = (size_t)r * D_ + k0 + s * 8;
            CP_ASYNC16(sbase + OFF_A + so, Ab + oa);
            CP_ASYNC16(sbase + OFF_BH + so, Bbh + oa);
            if (twop) CP_ASYNC16(sbase + OFF_BL + so, Bbl + oa);
        }
        CP_COMMIT();
    };

    load_stage(0);

    for (int c = 0; c < nch; c++) {
        if (c + 1 < nch) { load_stage(c + 1); CP_WAIT(1); }
        else             { CP_WAIT(0); }
        __syncthreads();

        const uint32_t sbase = sb + (c % NSTAGE) * STG;
#pragma unroll
        for (int ks = 0; ks < 4; ks++) {
            uint32_t ah[4][4], bh[2][4], bl[2][4];
            const int ar = wm * 64 + (lid & 15);
            const int ag = ks * 2 + (lid >> 4);
#pragma unroll
            for (int im = 0; im < 4; im++)
                ldsm4(ah[im], sbase + OFF_A + SWR(ar + im * 16, ag));
            const int br = wn * 32 + (lid & 7) + ((lid >> 4) & 1) * 8;
            const int bg = ks * 2 + ((lid >> 3) & 1);
#pragma unroll
            for (int g = 0; g < 2; g++) {
                uint32_t off = SWR(br + g * 16, bg);
                ldsm4(bh[g], sbase + OFF_BH + off);
                if (twop) ldsm4(bl[g], sbase + OFF_BL + off);
            }
#pragma unroll
            for (int im = 0; im < 4; im++)
#pragma unroll
                for (int in = 0; in < 4; in++) {
                    int g = in >> 1, s2 = (in & 1) * 2;
                    mma_f16(acc[im][in], ah[im], &bh[g][s2]);
                    if (twop) mma_f16(acc[im][in], ah[im], &bl[g][s2]);
                }
        }
        if (twop) __syncthreads();   // 2-stage WAR guard; 3-stage ring exempt
    }

    const int group = lid >> 2, tid4 = lid & 3;

    auto emit = [&](int m, int n, float v) {
        v = (v + bsel[n]) * scale;
        if (zz == 0) {
            kh[(size_t)m * D_ + n] = __float2half_rn(v);
        } else if (zz == 1) {
            int bb = m >> 12, kv = m & (LKV_ - 1);
            vth[((size_t)(bb * D_ + n)) * LKV_ + kv] = __float2half_rn(v);
        } else {
            qh[(size_t)m * D_ + n] = __float2half_rn(v);
        }
    };

#pragma unroll
    for (int im = 0; im < 4; im++)
#pragma unroll
        for (int in = 0; in < 4; in++) {
            int row = m0 + wm * 64 + im * 16 + group;
            int col = n0 + wn * 32 + in * 8 + tid4 * 2;
            emit(row,     col,     acc[im][in][0]);
            emit(row,     col + 1, acc[im][in][1]);
            emit(row + 8, col,     acc[im][in][2]);
            emit(row + 8, col + 1, acc[im][in][3]);
        }
}

// ---------------------------------------------------------------------------
// O projection: 2-pass fp16 -> fp32 out. K-chunk 64, 2-stage.
// ---------------------------------------------------------------------------
__global__ __launch_bounds__(256) void oproj_kernel(
    const __half* __restrict__ A,
    const __half* __restrict__ Bh, const __half* __restrict__ Bl,
    float* __restrict__ Cf, const float* __restrict__ bias)
{
    extern __shared__ char smem[];
    const uint32_t sb = smem_u32(smem);
    const int t = threadIdx.x, wid = t >> 5, lid = t & 31;
    const int wm = wid & 1, wn = wid >> 1;
    const int m0 = blockIdx.y * 128, n0 = blockIdx.x * 128;
    const int STG = 49152;

    const __half* Ab  = A + (size_t)m0 * D_;
    const __half* Bbh = Bh + (size_t)n0 * D_;
    const __half* Bbl = Bl + (size_t)n0 * D_;

    float acc[4][4][4];
#pragma unroll
    for (int i = 0; i < 4; i++)
#pragma unroll
        for (int j = 0; j < 4; j++)
#pragma unroll
            for (int r = 0; r < 4; r++) acc[i][j][r] = 0.f;

    auto load_stage = [&](int c) {
        const int k0 = c << 6;
        const uint32_t sbase = sb + (c & 1) * STG;
#pragma unroll
        for (int i = 0; i < 4; i++) {
            int idx = t + i * 256;
            int r = idx >> 3, s = idx & 7;
            uint32_t so = SWR(r, s);
            size_t oa = (size_t)r * D_ + k0 + s * 8;
            CP_ASYNC16(sbase + OFF_A + so, Ab + oa);
            CP_ASYNC16(sbase + OFF_BH + so, Bbh + oa);
            CP_ASYNC16(sbase + OFF_BL + so, Bbl + oa);
        }
        CP_COMMIT();
    };

    load_stage(0);
    const int nch = D_ >> 6;
    for (int c = 0; c < nch; c++) {
        if (c + 1 < nch) { load_stage(c + 1); CP_WAIT(1); }
        else             { CP_WAIT(0); }
        __syncthreads();
        const uint32_t sbase = sb + (c & 1) * STG;
#pragma unroll
        for (int ks = 0; ks < 4; ks++) {
            uint32_t ah[4][4], bh[2][4], bl[2][4];
            const int ar = wm * 64 + (lid & 15);
            const int ag = ks * 2 + (lid >> 4);
#pragma unroll
            for (int im = 0; im < 4; im++)
                ldsm4(ah[im], sbase + OFF_A + SWR(ar + im * 16, ag));
            const int br = wn * 32 + (lid & 7) + ((lid >> 4) & 1) * 8;
            const int bg = ks * 2 + ((lid >> 3) & 1);
#pragma unroll
            for (int g = 0; g < 2; g++) {
                uint32_t off = SWR(br + g * 16, bg);
                ldsm4(bh[g], sbase + OFF_BH + off);
                ldsm4(bl[g], sbase + OFF_BL + off);
            }
#pragma unroll
            for (int im = 0; im < 4; im++)
#pragma unroll
                for (int in = 0; in < 4; in++) {
                    int g = in >> 1, s2 = (in & 1) * 2;
                    mma_f16(acc[im][in], ah[im], &bh[g][s2]);
                    mma_f16(acc[im][in], ah[im], &bl[g][s2]);
                }
        }
        __syncthreads();
    }

    const int group = lid >> 2, tid4 = lid & 3;
#pragma unroll
    for (int im = 0; im < 4; im++)
#pragma unroll
        for (int in = 0; in < 4; in++) {
            int row = m0 + wm * 64 + im * 16 + group;
            int col = n0 + wn * 32 + in * 8 + tid4 * 2;
            Cf[(size_t)row * D_ + col]           = acc[im][in][0] + bias[col];
            Cf[(size_t)row * D_ + col + 1]       = acc[im][in][1] + bias[col + 1];
            Cf[(size_t)(row + 8) * D_ + col]     = acc[im][in][2] + bias[col];
            Cf[(size_t)(row + 8) * D_ + col + 1] = acc[im][in][3] + bias[col + 1];
        }
}

// ---------------------------------------------------------------------------
// Flash attention, fp16 single-pass, exp2 softmax. Q-tile 64, 128 threads,
// 3-stage KV ring. Q fragments hoisted to registers (loop-invariant).
// ---------------------------------------------------------------------------
#define F_Q    0
#define F_ST   16384
#define F_STSZ 32768
#define F_K    0
#define F_V    16384
#define FLASH_SMEM (F_ST + 3 * F_STSZ)   // 114688

__global__ __launch_bounds__(128, 2) void flash_kernel(
    const __half* __restrict__ q, const __half* __restrict__ k,
    const __half* __restrict__ vt, __half* __restrict__ ct)
{
    extern __shared__ char smem[];
    const uint32_t sb = smem_u32(smem);
    const int t = threadIdx.x, wid = t >> 5, lid = t & 31;
    const int z = blockIdx.y, zb = z >> 2, zh = z & 3;
    const int q0 = blockIdx.x * 64;

#pragma unroll
    for (int i = 0; i < 8; i++) {
        int idx = t + i * 128;
        int r = idx >> 4, g = idx & 15;
        const __half* gp = q + ((size_t)(zb * LQ_ + q0 + r)) * D_ + zh * HD_ + g * 8;
        CP_ASYNC16(sb + F_Q + SWQ(r, g), gp);
    }
    CP_COMMIT();

    auto load_kv = [&](int kt2) {
        const int kv0 = kt2 * 64;
        const uint32_t stb = sb + F_ST + (kt2 % 3) * F_STSZ;
#pragma unroll
        for (int i = 0; i < 8; i++) {
            int idx = t + i * 128;
            int r = idx >> 4, g = idx & 15;
            const __half* gp = k + ((size_t)(zb * LKV_ + kv0 + r)) * D_ + zh * HD_ + g * 8;
            CP_ASYNC16(stb + F_K + SWQ(r, g), gp);
        }
#pragma unroll
        for (int i = 0; i < 8; i++) {
            int idx = t + i * 128;
            int r = idx >> 3, g = idx & 7;
            const __half* gp = vt + ((size_t)(zb * D_ + zh * HD_ + r)) * LKV_ + kv0 + g * 8;
            CP_ASYNC16(stb + F_V + SWR(r, g), gp);
        }
        CP_COMMIT();
    };

    load_kv(0);

    // ---- hoist Q fragments (loop-invariant) into registers ----
    CP_WAIT(1);          // Q group complete (kv0 may still be in flight)
    __syncthreads();
    uint32_t aq[8][4];
    {
        const int ar = wid * 16 + (lid & 15);
#pragma unroll
        for (int ks = 0; ks < 8; ks++)
            ldsm4(aq[ks], sb + F_Q + SWQ(ar, ks * 2 + (lid >> 4)));
    }

    float oacc[16][4];
#pragma unroll
    for (int i = 0; i < 16; i++)
#pragma unroll
        for (int j = 0; j < 4; j++) oacc[i][j] = 0.f;
    float mr0 = -1e30f, mr1 = -1e30f, l0 = 0.f, l1 = 0.f;

    for (int kt = 0; kt < LKV_ / 64; kt++) {
        if (kt + 1 < LKV_ / 64) { load_kv(kt + 1); CP_WAIT(1); }
        else                    { CP_WAIT(0); }
        __syncthreads();
        const uint32_t stb = sb + F_ST + (kt % 3) * F_STSZ;

        float sacc[8][4];
#pragma unroll
        for (int i = 0; i < 8; i++)
#pragma unroll
            for (int j = 0; j < 4; j++) sacc[i][j] = 0.f;

#pragma unroll
        for (int ks = 0; ks < 8; ks++) {
#pragma unroll
            for (int jn = 0; jn < 4; jn++) {
                uint32_t bk4[4];
                const int br = jn * 16 + (lid & 7) + ((lid >> 4) & 1) * 8;
                const int bg = ks * 2 + ((lid >> 3) & 1);
                ldsm4(bk4, stb + F_K + SWQ(br, bg));
                mma_f16(sacc[2 * jn],     aq[ks], &bk4[0]);
                mma_f16(sacc[2 * jn + 1], aq[ks], &bk4[2]);
            }
        }

        float tm0 = -1e30f, tm1 = -1e30f;
#pragma unroll
        for (int i = 0; i < 8; i++) {
            tm0 = fmaxf(tm0, fmaxf(sacc[i][0], sacc[i][1]));
            tm1 = fmaxf(tm1, fmaxf(sacc[i][2], sacc[i][3]));
        }
        tm0 = fmaxf(tm0, __shfl_xor_sync(0xffffffffu, tm0, 1));
        tm0 = fmaxf(tm0, __shfl_xor_sync(0xffffffffu, tm0, 2));
        tm1 = fmaxf(tm1, __shfl_xor_sync(0xffffffffu, tm1, 1));
        tm1 = fmaxf(tm1, __shfl_xor_sync(0xffffffffu, tm1, 2));

        const float mn0 = fmaxf(mr0, tm0), mn1 = fmaxf(mr1, tm1);
        const float al0 = exp2f(mr0 - mn0), al1 = exp2f(mr1 - mn1);
        mr0 = mn0; mr1 = mn1;

        uint32_t phi[8][2];
        float ps0 = 0.f, ps1 = 0.f;
#pragma unroll
        for (int i = 0; i < 8; i++) {
            float p00 = exp2f(sacc[i][0] - mn0);
            float p01 = exp2f(sacc[i][1] - mn0);
            float p10 = exp2f(sacc[i][2] - mn1);
            float p11 = exp2f(sacc[i][3] - mn1);
            ps0 += p00 + p01; ps1 += p10 + p11;
            phi[i][0] = pack_h2(p00, p01);
            phi[i][1] = pack_h2(p10, p11);
        }
        l0 = l0 * al0 + ps0;
        l1 = l1 * al1 + ps1;
        if (al0 != 1.f || al1 != 1.f) {
#pragma unroll
            for (int i = 0; i < 16; i++) {
                oacc[i][0] *= al0; oacc[i][1] *= al0;
                oacc[i][2] *= al1; oacc[i][3] *= al1;
            }
        }

#pragma unroll
        for (int pk = 0; pk < 4; pk++) {
            uint32_t ap[4] = {phi[2 * pk][0], phi[2 * pk][1],
                              phi[2 * pk + 1][0], phi[2 * pk + 1][1]};
#pragma unroll
            for (int jn = 0; jn < 8; jn++) {
                uint32_t bv[4];
                const int vr = jn * 16 + (lid & 7) + ((lid >> 4) & 1) * 8;
                const int vg = pk * 2 + ((lid >> 3) & 1);
                ldsm4(bv, stb + F_V + SWR(vr, vg));
                mma_f16(oacc[2 * jn],     ap, &bv[0]);
                mma_f16(oacc[2 * jn + 1], ap, &bv[2]);
            }
        }
    }

    l0 += __shfl_xor_sync(0xffffffffu, l0, 1);
    l0 += __shfl_xor_sync(0xffffffffu, l0, 2);
    l1 += __shfl_xor_sync(0xffffffffu, l1, 1);
    l1 += __shfl_xor_sync(0xffffffffu, l1, 2);
    const float inv0 = 1.0f / l0, inv1 = 1.0f / l1;

    const int r = lid >> 2, c2 = (lid & 3) * 2;
    const int qg = q0 + wid * 16 + r;
    const size_t row0 = ((size_t)(zb * LQ_) + qg) * D_ + zh * HD_;
    const size_t row1 = row0 + 8 * D_;
#pragma unroll
    for (int jt = 0; jt < 16; jt++) {
        int col = jt * 8 + c2;
        *(uint32_t*)(ct + row0 + col) = pack_h2(oacc[jt][0] * inv0, oacc[jt][1] * inv0);
        *(uint32_t*)(ct + row1 + col) = pack_h2(oacc[jt][2] * inv1, oacc[jt][3] * inv1);
    }
}

// ---------------------------------------------------------------------------
extern "C" void kernel_launch(void* const* d_in, const int* in_sizes, int n_in,
                              void* d_out, int out_size)
{
    const float* x   = (const float*)d_in[0];
    const float* enc = (const float*)d_in[1];
    const float* Wq  = (const float*)d_in[2];
    const float* Wk  = (const float*)d_in[3];
    const float* Wv  = (const float*)d_in[4];
    const float* bq  = (const float*)d_in[5];
    const float* bk  = (const float*)d_in[6];
    const float* bv  = (const float*)d_in[7];
    const float* Wo  = (const float*)d_in[8];
    const float* bo  = (const float*)d_in[9];
    float* out = (float*)d_out;

    __half *xh, *eh, *wqh, *wql, *wk, *wv, *woh, *wol;
    __half *qh, *kh, *vth, *ct;
    cudaGetSymbolAddress((void**)&xh,  g_xh);
    cudaGetSymbolAddress((void**)&eh,  g_eh);
    cudaGetSymbolAddress((void**)&wqh, g_wqhi); cudaGetSymbolAddress((void**)&wql, g_wqlo);
    cudaGetSymbolAddress((void**)&wk,  g_wk);
    cudaGetSymbolAddress((void**)&wv,  g_wv);
    cudaGetSymbolAddress((void**)&woh, g_wohi); cudaGetSymbolAddress((void**)&wol, g_wolo);
    cudaGetSymbolAddress((void**)&qh,  g_qh);   cudaGetSymbolAddress((void**)&kh,  g_kh);
    cudaGetSymbolAddress((void**)&vth, g_vth);  cudaGetSymbolAddress((void**)&ct,  g_ct);

    cudaFuncSetAttribute((const void*)qkv_kernel,   cudaFuncAttributeMaxDynamicSharedMemorySize, GEMM_SMEM);
    cudaFuncSetAttribute((const void*)oproj_kernel, cudaFuncAttributeMaxDynamicSharedMemorySize, GEMM_SMEM);
    cudaFuncSetAttribute((const void*)flash_kernel, cudaFuncAttributeMaxDynamicSharedMemorySize, FLASH_SMEM);

    // 1) single prep launch
    prep_kernel<<<dim3(256, 6), 256>>>(x, enc, Wq, Wk, Wv, Wo,
                                       xh, eh, wqh, wql, wk, wv, woh, wol);

    // 2) merged Q+K+V projections (z: 0=K, 1=V transposed, 2=Q 2-pass)
    qkv_kernel<<<dim3(4, 128, 3), 256, GEMM_SMEM>>>(
        xh, eh, wqh, wql, wk, wv, qh, kh, vth, bq, bk, bv);

    // 3) fused flash attention (fp16, exp2, Q-in-regs) -> ctx fp16
    flash_kernel<<<dim3(LQ_ / 64, B_ * H_), 128, FLASH_SMEM>>>(qh, kh, vth, ct);

    // 4) output projection (2-pass) -> fp32 out
    oproj_kernel<<<dim3(4, 32), 256, GEMM_SMEM>>>(ct, woh, wol, out, bo);
}

// round 13
// speedup vs baseline: 1.0506x; 1.0506x over previous
#include <cuda_runtime.h>
#include <cuda_bf16.h>
#include <cuda_fp16.h>
#include <cstdint>
#include <math.h>

#define B_   4
#define LQ_  1024
#define LKV_ 4096
#define D_   512
#define H_   4
#define HD_  128
#define SCALE_ 0.08838834764831845f      // 1/sqrt(128)
#define LOG2E_ 1.4426950408889634f
#define QSCALE_ (SCALE_ * LOG2E_)        // logits emitted in log2 domain

// ---------------------------------------------------------------------------
// Helpers
// ---------------------------------------------------------------------------
__device__ __forceinline__ uint32_t smem_u32(const void* p) {
    uint32_t a;
    asm("{ .reg .u64 t; cvta.to.shared.u64 t, %1; cvt.u32.u64 %0, t; }" : "=r"(a) : "l"(p));
    return a;
}

#define CP_ASYNC16(sa, g) \
    asm volatile("cp.async.cg.shared.global [%0], [%1], 16;" :: "r"(sa), "l"(g))
#define CP_COMMIT() asm volatile("cp.async.commit_group;" ::: "memory")
#define CP_WAIT(n)  asm volatile("cp.async.wait_group %0;" :: "n"(n) : "memory")

__device__ __forceinline__ void ldsm4(uint32_t* r, uint32_t a) {
    asm volatile("ldmatrix.sync.aligned.m8n8.x4.shared.b16 {%0,%1,%2,%3}, [%4];"
                 : "=r"(r[0]), "=r"(r[1]), "=r"(r[2]), "=r"(r[3]) : "r"(a));
}
__device__ __forceinline__ void mma_f16(float* c, const uint32_t* a, const uint32_t* b) {
    asm volatile("mma.sync.aligned.m16n8k16.row.col.f32.f16.f16.f32 "
                 "{%0,%1,%2,%3}, {%4,%5,%6,%7}, {%8,%9}, {%0,%1,%2,%3};"
                 : "+f"(c[0]), "+f"(c[1]), "+f"(c[2]), "+f"(c[3])
                 : "r"(a[0]), "r"(a[1]), "r"(a[2]), "r"(a[3]), "r"(b[0]), "r"(b[1]));
}
__device__ __forceinline__ uint32_t pack_h2(float a, float b) {
    __half2 v = __floats2half2_rn(a, b);
    return *(uint32_t*)&v;
}

// 128B-row swizzle (8 granules of 16B per row), conflict-free for ldsm
#define SWR(r, g) ((uint32_t)(r) * 128 + ((uint32_t)((g) ^ ((r) & 7)) << 4))
// 256B-row swizzle (flash Q/K tiles)
#define SWQ(r, g) ((uint32_t)(r) * 256 + ((uint32_t)((g) ^ ((r) & 15)) << 4))

// ---------------------------------------------------------------------------
// Device scratch (allocation-free)
// ---------------------------------------------------------------------------
#define NX  ((size_t)B_ * LQ_ * D_)
#define NE  ((size_t)B_ * LKV_ * D_)
#define NW  ((size_t)D_ * D_)

__device__ __half g_xh[NX];
__device__ __half g_eh[NE];
__device__ __half g_wqhi[NW], g_wqlo[NW];
__device__ __half g_wk[NW];
__device__ __half g_wv[NW];
__device__ __half g_wohi[NW], g_wolo[NW];
__device__ __half g_qh[NX];
__device__ __half g_kh[NE];
__device__ __half g_vth[NE];           // transposed [b][h*HD+d][lkv]
__device__ __half g_ct[NX];

// ---------------------------------------------------------------------------
// Single prep kernel: y selects task
// ---------------------------------------------------------------------------
__global__ __launch_bounds__(256) void prep_kernel(
    const float* __restrict__ x, const float* __restrict__ enc,
    const float* __restrict__ Wq, const float* __restrict__ Wk,
    const float* __restrict__ Wv, const float* __restrict__ Wo,
    __half* __restrict__ xh, __half* __restrict__ eh,
    __half* __restrict__ wqh, __half* __restrict__ wql,
    __half* __restrict__ wk, __half* __restrict__ wv,
    __half* __restrict__ woh, __half* __restrict__ wol)
{
    const int which = blockIdx.y;
    const int stride = gridDim.x * blockDim.x;
    const int tid0 = blockIdx.x * blockDim.x + threadIdx.x;
    if (which <= 1 || which == 3 || which == 4) {
        const float* in = (which == 0) ? x : (which == 1) ? enc : (which == 3) ? Wk : Wv;
        __half* outp    = (which == 0) ? xh : (which == 1) ? eh : (which == 3) ? wk : wv;
        const int n4    = (which == 0) ? (int)(NX / 4) : (which == 1) ? (int)(NE / 4) : (int)(NW / 4);
        for (int i = tid0; i < n4; i += stride) {
            float4 v = ((const float4*)in)[i];
            ((uint2*)outp)[i] = make_uint2(pack_h2(v.x, v.y), pack_h2(v.z, v.w));
        }
    } else {
        const float* in = (which == 2) ? Wq : Wo;
        __half* hi = (which == 2) ? wqh : woh;
        __half* lo = (which == 2) ? wql : wol;
        const int n4 = (int)(NW / 4);
        for (int i = tid0; i < n4; i += stride) {
            float4 v = ((const float4*)in)[i];
            float f[4] = {v.x, v.y, v.z, v.w};
            float h[4], l[4];
#pragma unroll
            for (int j = 0; j < 4; j++) {
                h[j] = __half2float(__float2half_rn(f[j]));
                l[j] = f[j] - h[j];
            }
            ((uint2*)hi)[i] = make_uint2(pack_h2(h[0], h[1]), pack_h2(h[2], h[3]));
            ((uint2*)lo)[i] = make_uint2(pack_h2(l[0], l[1]), pack_h2(l[2], l[3]));
        }
    }
}

// ---------------------------------------------------------------------------
// Generic NT GEMM, fp16, K-chunk 64. CTA tile 128x128, warp tile 64x32.
// PASSES=1: 3-stage ring, no trailing barrier. PASSES=2: 2-stage, both barriers.
// MODE 0: fp32 out. MODE 3: fp16 out. MODE 5: merged KV (z: 0=K fp16, 1=V transposed).
// (R11-proven templated version — compile-time code shape.)
// ---------------------------------------------------------------------------
#define OFF_A  0
#define OFF_BH 16384
#define OFF_BL 32768
#define GEMM_SMEM 98304   // P1: 3 x 32768; P2: 2 x 49152

template <int MODE, int PASSES>
__global__ __launch_bounds__(256) void gemm_kernel(
    const __half* __restrict__ A, int lda,
    const __half* __restrict__ Bh, const __half* __restrict__ Bl,
    const __half* __restrict__ Bh2, int ldb,
    float* __restrict__ Cf, __half* __restrict__ Ch, __half* __restrict__ Ch2,
    int ldc, int K, const float* __restrict__ bias, const float* __restrict__ bias2,
    float scale)
{
    extern __shared__ char smem[];
    const uint32_t sb = smem_u32(smem);
    const int t = threadIdx.x, wid = t >> 5, lid = t & 31;
    const int wm = wid & 1, wn = wid >> 1;
    const int m0 = blockIdx.y * 128, n0 = blockIdx.x * 128;
    const int STG = (PASSES == 2) ? 49152 : 32768;
    const int NSTAGE = (PASSES == 2) ? 2 : 3;

    const int zz = (MODE == 5) ? blockIdx.z : 0;
    const __half* Bsel = (MODE == 5 && zz) ? Bh2 : Bh;
    const float* bsel  = (MODE == 5 && zz) ? bias2 : bias;

    const __half* Ab  = A + (size_t)m0 * lda;
    const __half* Bbh = Bsel + (size_t)n0 * ldb;
    const __half* Bbl = (PASSES == 2) ? (Bl + (size_t)n0 * ldb) : nullptr;

    float acc[4][4][4];
#pragma unroll
    for (int i = 0; i < 4; i++)
#pragma unroll
        for (int j = 0; j < 4; j++)
#pragma unroll
            for (int r = 0; r < 4; r++) acc[i][j][r] = 0.f;

    const int nch = K >> 6;   // chunks of 64

    auto load_stage = [&](int c) {
        const int k0 = c << 6;
        const uint32_t sbase = sb + (c % NSTAGE) * STG;
#pragma unroll
        for (int i = 0; i < 4; i++) {
            int idx = t + i * 256;
            int r = idx >> 3, s = idx & 7;
            uint32_t so = SWR(r, s);
            size_t oa = (size_t)r * lda + k0 + s * 8;
            size_t ob = (size_t)r * ldb + k0 + s * 8;
            CP_ASYNC16(sbase + OFF_A + so, Ab + oa);
            CP_ASYNC16(sbase + OFF_BH + so, Bbh + ob);
            if (PASSES == 2) CP_ASYNC16(sbase + OFF_BL + so, Bbl + ob);
        }
        CP_COMMIT();
    };

    load_stage(0);

    for (int c = 0; c < nch; c++) {
        if (c + 1 < nch) { load_stage(c + 1); CP_WAIT(1); }
        else             { CP_WAIT(0); }
        __syncthreads();

        const uint32_t sbase = sb + (c % NSTAGE) * STG;
#pragma unroll
        for (int ks = 0; ks < 4; ks++) {
            uint32_t ah[4][4], bh[2][4], bl[2][4];
            const int ar = wm * 64 + (lid & 15);
            const int ag = ks * 2 + (lid >> 4);
#pragma unroll
            for (int im = 0; im < 4; im++)
                ldsm4(ah[im], sbase + OFF_A + SWR(ar + im * 16, ag));
            const int br = wn * 32 + (lid & 7) + ((lid >> 4) & 1) * 8;
            const int bg = ks * 2 + ((lid >> 3) & 1);
#pragma unroll
            for (int g = 0; g < 2; g++) {
                uint32_t off = SWR(br + g * 16, bg);
                ldsm4(bh[g], sbase + OFF_BH + off);
                if (PASSES == 2) ldsm4(bl[g], sbase + OFF_BL + off);
            }
#pragma unroll
            for (int im = 0; im < 4; im++)
#pragma unroll
                for (int in = 0; in < 4; in++) {
                    int g = in >> 1, s2 = (in & 1) * 2;
                    mma_f16(acc[im][in], ah[im], &bh[g][s2]);
                    if (PASSES == 2) mma_f16(acc[im][in], ah[im], &bl[g][s2]);
                }
        }
        if (PASSES == 2) __syncthreads();   // 2-stage WAR guard; 3-stage ring exempt
    }

    const int group = lid >> 2, tid4 = lid & 3;

    auto emit = [&](int m, int n, float v) {
        if (bsel) v += bsel[n];
        v *= scale;
        if (MODE == 0) {
            Cf[(size_t)m * ldc + n] = v;
        } else if (MODE == 3) {
            Ch[(size_t)m * ldc + n] = __float2half_rn(v);
        } else {  // MODE 5
            if (zz == 0) {
                Ch[(size_t)m * ldc + n] = __float2half_rn(v);
            } else {
                int bb = m >> 12, kv = m & (LKV_ - 1);
                Ch2[((size_t)(bb * D_ + n)) * LKV_ + kv] = __float2half_rn(v);
            }
        }
    };

#pragma unroll
    for (int im = 0; im < 4; im++)
#pragma unroll
        for (int in = 0; in < 4; in++) {
            int row = m0 + wm * 64 + im * 16 + group;
            int col = n0 + wn * 32 + in * 8 + tid4 * 2;
            emit(row,     col,     acc[im][in][0]);
            emit(row,     col + 1, acc[im][in][1]);
            emit(row + 8, col,     acc[im][in][2]);
            emit(row + 8, col + 1, acc[im][in][3]);
        }
}

// ---------------------------------------------------------------------------
// Flash attention, fp16 single-pass, exp2 softmax. Q-tile 64, 128 threads,
// 3-stage KV ring, single barrier per iteration.
// Q fragments hoisted to registers (loop-invariant) — the R12 change kept.
// ---------------------------------------------------------------------------
#define F_Q    0
#define F_ST   16384
#define F_STSZ 32768
#define F_K    0
#define F_V    16384
#define FLASH_SMEM (F_ST + 3 * F_STSZ)   // 114688

__global__ __launch_bounds__(128, 2) void flash_kernel(
    const __half* __restrict__ q, const __half* __restrict__ k,
    const __half* __restrict__ vt, __half* __restrict__ ct)
{
    extern __shared__ char smem[];
    const uint32_t sb = smem_u32(smem);
    const int t = threadIdx.x, wid = t >> 5, lid = t & 31;
    const int z = blockIdx.y, zb = z >> 2, zh = z & 3;
    const int q0 = blockIdx.x * 64;

#pragma unroll
    for (int i = 0; i < 8; i++) {
        int idx = t + i * 128;
        int r = idx >> 4, g = idx & 15;
        const __half* gp = q + ((size_t)(zb * LQ_ + q0 + r)) * D_ + zh * HD_ + g * 8;
        CP_ASYNC16(sb + F_Q + SWQ(r, g), gp);
    }
    CP_COMMIT();

    auto load_kv = [&](int kt2) {
        const int kv0 = kt2 * 64;
        const uint32_t stb = sb + F_ST + (kt2 % 3) * F_STSZ;
#pragma unroll
        for (int i = 0; i < 8; i++) {
            int idx = t + i * 128;
            int r = idx >> 4, g = idx & 15;
            const __half* gp = k + ((size_t)(zb * LKV_ + kv0 + r)) * D_ + zh * HD_ + g * 8;
            CP_ASYNC16(stb + F_K + SWQ(r, g), gp);
        }
#pragma unroll
        for (int i = 0; i < 8; i++) {
            int idx = t + i * 128;
            int r = idx >> 3, g = idx & 7;
            const __half* gp = vt + ((size_t)(zb * D_ + zh * HD_ + r)) * LKV_ + kv0 + g * 8;
            CP_ASYNC16(stb + F_V + SWR(r, g), gp);
        }
        CP_COMMIT();
    };

    load_kv(0);

    // ---- hoist Q fragments (loop-invariant) into registers ----
    CP_WAIT(1);          // Q group complete (kv0 may still be in flight)
    __syncthreads();
    uint32_t aq[8][4];
    {
        const int ar = wid * 16 + (lid & 15);
#pragma unroll
        for (int ks = 0; ks < 8; ks++)
            ldsm4(aq[ks], sb + F_Q + SWQ(ar, ks * 2 + (lid >> 4)));
    }

    float oacc[16][4];
#pragma unroll
    for (int i = 0; i < 16; i++)
#pragma unroll
        for (int j = 0; j < 4; j++) oacc[i][j] = 0.f;
    float mr0 = -1e30f, mr1 = -1e30f, l0 = 0.f, l1 = 0.f;

    for (int kt = 0; kt < LKV_ / 64; kt++) {
        if (kt + 1 < LKV_ / 64) { load_kv(kt + 1); CP_WAIT(1); }
        else                    { CP_WAIT(0); }
        __syncthreads();
        const uint32_t stb = sb + F_ST + (kt % 3) * F_STSZ;

        float sacc[8][4];
#pragma unroll
        for (int i = 0; i < 8; i++)
#pragma unroll
            for (int j = 0; j < 4; j++) sacc[i][j] = 0.f;

#pragma unroll
        for (int ks = 0; ks < 8; ks++) {
#pragma unroll
            for (int jn = 0; jn < 4; jn++) {
                uint32_t bk4[4];
                const int br = jn * 16 + (lid & 7) + ((lid >> 4) & 1) * 8;
                const int bg = ks * 2 + ((lid >> 3) & 1);
                ldsm4(bk4, stb + F_K + SWQ(br, bg));
                mma_f16(sacc[2 * jn],     aq[ks], &bk4[0]);
                mma_f16(sacc[2 * jn + 1], aq[ks], &bk4[2]);
            }
        }

        float tm0 = -1e30f, tm1 = -1e30f;
#pragma unroll
        for (int i = 0; i < 8; i++) {
            tm0 = fmaxf(tm0, fmaxf(sacc[i][0], sacc[i][1]));
            tm1 = fmaxf(tm1, fmaxf(sacc[i][2], sacc[i][3]));
        }
        tm0 = fmaxf(tm0, __shfl_xor_sync(0xffffffffu, tm0, 1));
        tm0 = fmaxf(tm0, __shfl_xor_sync(0xffffffffu, tm0, 2));
        tm1 = fmaxf(tm1, __shfl_xor_sync(0xffffffffu, tm1, 1));
        tm1 = fmaxf(tm1, __shfl_xor_sync(0xffffffffu, tm1, 2));

        const float mn0 = fmaxf(mr0, tm0), mn1 = fmaxf(mr1, tm1);
        const float al0 = exp2f(mr0 - mn0), al1 = exp2f(mr1 - mn1);
        mr0 = mn0; mr1 = mn1;

        uint32_t phi[8][2];
        float ps0 = 0.f, ps1 = 0.f;
#pragma unroll
        for (int i = 0; i < 8; i++) {
            float p00 = exp2f(sacc[i][0] - mn0);
            float p01 = exp2f(sacc[i][1] - mn0);
            float p10 = exp2f(sacc[i][2] - mn1);
            float p11 = exp2f(sacc[i][3] - mn1);
            ps0 += p00 + p01; ps1 += p10 + p11;
            phi[i][0] = pack_h2(p00, p01);
            phi[i][1] = pack_h2(p10, p11);
        }
        l0 = l0 * al0 + ps0;
        l1 = l1 * al1 + ps1;
        if (al0 != 1.f || al1 != 1.f) {
#pragma unroll
            for (int i = 0; i < 16; i++) {
                oacc[i][0] *= al0; oacc[i][1] *= al0;
                oacc[i][2] *= al1; oacc[i][3] *= al1;
            }
        }

#pragma unroll
        for (int pk = 0; pk < 4; pk++) {
            uint32_t ap[4] = {phi[2 * pk][0], phi[2 * pk][1],
                              phi[2 * pk + 1][0], phi[2 * pk + 1][1]};
#pragma unroll
            for (int jn = 0; jn < 8; jn++) {
                uint32_t bv[4];
                const int vr = jn * 16 + (lid & 7) + ((lid >> 4) & 1) * 8;
                const int vg = pk * 2 + ((lid >> 3) & 1);
                ldsm4(bv, stb + F_V + SWR(vr, vg));
                mma_f16(oacc[2 * jn],     ap, &bv[0]);
                mma_f16(oacc[2 * jn + 1], ap, &bv[2]);
            }
        }
    }

    l0 += __shfl_xor_sync(0xffffffffu, l0, 1);
    l0 += __shfl_xor_sync(0xffffffffu, l0, 2);
    l1 += __shfl_xor_sync(0xffffffffu, l1, 1);
    l1 += __shfl_xor_sync(0xffffffffu, l1, 2);
    const float inv0 = 1.0f / l0, inv1 = 1.0f / l1;

    const int r = lid >> 2, c2 = (lid & 3) * 2;
    const int qg = q0 + wid * 16 + r;
    const size_t row0 = ((size_t)(zb * LQ_) + qg) * D_ + zh * HD_;
    const size_t row1 = row0 + 8 * D_;
#pragma unroll
    for (int jt = 0; jt < 16; jt++) {
        int col = jt * 8 + c2;
        *(uint32_t*)(ct + row0 + col) = pack_h2(oacc[jt][0] * inv0, oacc[jt][1] * inv0);
        *(uint32_t*)(ct + row1 + col) = pack_h2(oacc[jt][2] * inv1, oacc[jt][3] * inv1);
    }
}

// ---------------------------------------------------------------------------
extern "C" void kernel_launch(void* const* d_in, const int* in_sizes, int n_in,
                              void* d_out, int out_size)
{
    const float* x   = (const float*)d_in[0];
    const float* enc = (const float*)d_in[1];
    const float* Wq  = (const float*)d_in[2];
    const float* Wk  = (const float*)d_in[3];
    const float* Wv  = (const float*)d_in[4];
    const float* bq  = (const float*)d_in[5];
    const float* bk  = (const float*)d_in[6];
    const float* bv  = (const float*)d_in[7];
    const float* Wo  = (const float*)d_in[8];
    const float* bo  = (const float*)d_in[9];
    float* out = (float*)d_out;

    __half *xh, *eh, *wqh, *wql, *wk, *wv, *woh, *wol;
    __half *qh, *kh, *vth, *ct;
    cudaGetSymbolAddress((void**)&xh,  g_xh);
    cudaGetSymbolAddress((void**)&eh,  g_eh);
    cudaGetSymbolAddress((void**)&wqh, g_wqhi); cudaGetSymbolAddress((void**)&wql, g_wqlo);
    cudaGetSymbolAddress((void**)&wk,  g_wk);
    cudaGetSymbolAddress((void**)&wv,  g_wv);
    cudaGetSymbolAddress((void**)&woh, g_wohi); cudaGetSymbolAddress((void**)&wol, g_wolo);
    cudaGetSymbolAddress((void**)&qh,  g_qh);   cudaGetSymbolAddress((void**)&kh,  g_kh);
    cudaGetSymbolAddress((void**)&vth, g_vth);  cudaGetSymbolAddress((void**)&ct,  g_ct);

    cudaFuncSetAttribute((const void*)gemm_kernel<0, 2>, cudaFuncAttributeMaxDynamicSharedMemorySize, GEMM_SMEM);
    cudaFuncSetAttribute((const void*)gemm_kernel<3, 2>, cudaFuncAttributeMaxDynamicSharedMemorySize, GEMM_SMEM);
    cudaFuncSetAttribute((const void*)gemm_kernel<5, 1>, cudaFuncAttributeMaxDynamicSharedMemorySize, GEMM_SMEM);
    cudaFuncSetAttribute((const void*)flash_kernel, cudaFuncAttributeMaxDynamicSharedMemorySize, FLASH_SMEM);

    // 1) single prep launch
    prep_kernel<<<dim3(256, 6), 256>>>(x, enc, Wq, Wk, Wv, Wo,
                                       xh, eh, wqh, wql, wk, wv, woh, wol);

    // 2) Q projection (2-pass, pre-scaled by log2e/sqrt(HD))
    gemm_kernel<3, 2><<<dim3(4, 32), 256, GEMM_SMEM>>>(
        xh, D_, wqh, wql, nullptr, D_, nullptr, qh, nullptr, D_, D_, bq, nullptr, QSCALE_);

    // 3) merged K+V projections (1-pass, z: 0=K, 1=V transposed)
    gemm_kernel<5, 1><<<dim3(4, 128, 2), 256, GEMM_SMEM>>>(
        eh, D_, wk, nullptr, wv, D_, nullptr, kh, vth, D_, D_, bk, bv, 1.0f);

    // 4) fused flash attention (fp16, exp2, Q-in-regs) -> ctx fp16
    flash_kernel<<<dim3(LQ_ / 64, B_ * H_), 128, FLASH_SMEM>>>(qh, kh, vth, ct);

    // 5) output projection (2-pass) -> fp32 out
    gemm_kernel<0, 2><<<dim3(4, 32), 256, GEMM_SMEM>>>(
        ct, D_, woh, wol, nullptr, D_, out, nullptr, nullptr, D_, D_, bo, nullptr, 1.0f);
}

// round 14
// speedup vs baseline: 1.0747x; 1.0229x over previous
#include <cuda_runtime.h>
#include <cuda_bf16.h>
#include <cuda_fp16.h>
#include <cstdint>
#include <math.h>

#define B_   4
#define LQ_  1024
#define LKV_ 4096
#define D_   512
#define H_   4
#define HD_  128
#define SCALE_ 0.08838834764831845f      // 1/sqrt(128)
#define LOG2E_ 1.4426950408889634f
#define QSCALE_ (SCALE_ * LOG2E_)        // logits emitted in log2 domain

// ---------------------------------------------------------------------------
// Helpers
// ---------------------------------------------------------------------------
__device__ __forceinline__ uint32_t smem_u32(const void* p) {
    uint32_t a;
    asm("{ .reg .u64 t; cvta.to.shared.u64 t, %1; cvt.u32.u64 %0, t; }" : "=r"(a) : "l"(p));
    return a;
}

#define CP_ASYNC16(sa, g) \
    asm volatile("cp.async.cg.shared.global [%0], [%1], 16;" :: "r"(sa), "l"(g))
#define CP_COMMIT() asm volatile("cp.async.commit_group;" ::: "memory")
#define CP_WAIT(n)  asm volatile("cp.async.wait_group %0;" :: "n"(n) : "memory")

__device__ __forceinline__ void ldsm4(uint32_t* r, uint32_t a) {
    asm volatile("ldmatrix.sync.aligned.m8n8.x4.shared.b16 {%0,%1,%2,%3}, [%4];"
                 : "=r"(r[0]), "=r"(r[1]), "=r"(r[2]), "=r"(r[3]) : "r"(a));
}
__device__ __forceinline__ void mma_f16(float* c, const uint32_t* a, const uint32_t* b) {
    asm volatile("mma.sync.aligned.m16n8k16.row.col.f32.f16.f16.f32 "
                 "{%0,%1,%2,%3}, {%4,%5,%6,%7}, {%8,%9}, {%0,%1,%2,%3};"
                 : "+f"(c[0]), "+f"(c[1]), "+f"(c[2]), "+f"(c[3])
                 : "r"(a[0]), "r"(a[1]), "r"(a[2]), "r"(a[3]), "r"(b[0]), "r"(b[1]));
}
__device__ __forceinline__ uint32_t pack_h2(float a, float b) {
    __half2 v = __floats2half2_rn(a, b);
    return *(uint32_t*)&v;
}

// 128B-row swizzle (8 granules of 16B per row), conflict-free for ldsm
#define SWR(r, g) ((uint32_t)(r) * 128 + ((uint32_t)((g) ^ ((r) & 7)) << 4))
// 256B-row swizzle (flash Q/K tiles)
#define SWQ(r, g) ((uint32_t)(r) * 256 + ((uint32_t)((g) ^ ((r) & 15)) << 4))

// ---------------------------------------------------------------------------
// Device scratch (allocation-free)
// ---------------------------------------------------------------------------
#define NX  ((size_t)B_ * LQ_ * D_)
#define NE  ((size_t)B_ * LKV_ * D_)
#define NW  ((size_t)D_ * D_)

__device__ __half g_xh[NX];
__device__ __half g_eh[NE];
__device__ __half g_wqhi[NW], g_wqlo[NW];
__device__ __half g_wk[NW];
__device__ __half g_wv[NW];
__device__ __half g_wohi[NW], g_wolo[NW];
__device__ __half g_qh[NX];
__device__ __half g_kh[NE];
__device__ __half g_vth[NE];           // transposed [b][h*HD+d][lkv]
__device__ __half g_ct[NX];

// ---------------------------------------------------------------------------
// Single prep kernel: y selects task
// ---------------------------------------------------------------------------
__global__ __launch_bounds__(256) void prep_kernel(
    const float* __restrict__ x, const float* __restrict__ enc,
    const float* __restrict__ Wq, const float* __restrict__ Wk,
    const float* __restrict__ Wv, const float* __restrict__ Wo,
    __half* __restrict__ xh, __half* __restrict__ eh,
    __half* __restrict__ wqh, __half* __restrict__ wql,
    __half* __restrict__ wk, __half* __restrict__ wv,
    __half* __restrict__ woh, __half* __restrict__ wol)
{
    const int which = blockIdx.y;
    const int stride = gridDim.x * blockDim.x;
    const int tid0 = blockIdx.x * blockDim.x + threadIdx.x;
    if (which <= 1 || which == 3 || which == 4) {
        const float* in = (which == 0) ? x : (which == 1) ? enc : (which == 3) ? Wk : Wv;
        __half* outp    = (which == 0) ? xh : (which == 1) ? eh : (which == 3) ? wk : wv;
        const int n4    = (which == 0) ? (int)(NX / 4) : (which == 1) ? (int)(NE / 4) : (int)(NW / 4);
        for (int i = tid0; i < n4; i += stride) {
            float4 v = ((const float4*)in)[i];
            ((uint2*)outp)[i] = make_uint2(pack_h2(v.x, v.y), pack_h2(v.z, v.w));
        }
    } else {
        const float* in = (which == 2) ? Wq : Wo;
        __half* hi = (which == 2) ? wqh : woh;
        __half* lo = (which == 2) ? wql : wol;
        const int n4 = (int)(NW / 4);
        for (int i = tid0; i < n4; i += stride) {
            float4 v = ((const float4*)in)[i];
            float f[4] = {v.x, v.y, v.z, v.w};
            float h[4], l[4];
#pragma unroll
            for (int j = 0; j < 4; j++) {
                h[j] = __half2float(__float2half_rn(f[j]));
                l[j] = f[j] - h[j];
            }
            ((uint2*)hi)[i] = make_uint2(pack_h2(h[0], h[1]), pack_h2(h[2], h[3]));
            ((uint2*)lo)[i] = make_uint2(pack_h2(l[0], l[1]), pack_h2(l[2], l[3]));
        }
    }
}

// ---------------------------------------------------------------------------
// Merged K+V projection (R11-proven): 1-pass fp16, K-chunk 64, 3-stage ring,
// no trailing barrier. z: 0 = K (row-major fp16), 1 = V (transposed fp16).
// CTA tile 128x128, warp tile 64x32.
// ---------------------------------------------------------------------------
#define OFF_A  0
#define OFF_BH 16384
#define KV_SMEM 98304   // 3 stages x 32768

__global__ __launch_bounds__(256) void kv_kernel(
    const __half* __restrict__ A,
    const __half* __restrict__ Wk_, const __half* __restrict__ Wv_,
    __half* __restrict__ kh, __half* __restrict__ vth,
    const float* __restrict__ bk, const float* __restrict__ bv)
{
    extern __shared__ char smem[];
    const uint32_t sb = smem_u32(smem);
    const int t = threadIdx.x, wid = t >> 5, lid = t & 31;
    const int wm = wid & 1, wn = wid >> 1;
    const int m0 = blockIdx.y * 128, n0 = blockIdx.x * 128;
    const int zz = blockIdx.z;

    const __half* Bsel = zz ? Wv_ : Wk_;
    const float* bsel  = zz ? bv : bk;

    const __half* Ab  = A + (size_t)m0 * D_;
    const __half* Bbh = Bsel + (size_t)n0 * D_;

    float acc[4][4][4];
#pragma unroll
    for (int i = 0; i < 4; i++)
#pragma unroll
        for (int j = 0; j < 4; j++)
#pragma unroll
            for (int r = 0; r < 4; r++) acc[i][j][r] = 0.f;

    const int nch = D_ >> 6;

    auto load_stage = [&](int c) {
        const int k0 = c << 6;
        const uint32_t sbase = sb + (c % 3) * 32768;
#pragma unroll
        for (int i = 0; i < 4; i++) {
            int idx = t + i * 256;
            int r = idx >> 3, s = idx & 7;
            uint32_t so = SWR(r, s);
            size_t oa = (size_t)r * D_ + k0 + s * 8;
            CP_ASYNC16(sbase + OFF_A + so, Ab + oa);
            CP_ASYNC16(sbase + OFF_BH + so, Bbh + oa);
        }
        CP_COMMIT();
    };

    load_stage(0);

    for (int c = 0; c < nch; c++) {
        if (c + 1 < nch) { load_stage(c + 1); CP_WAIT(1); }
        else             { CP_WAIT(0); }
        __syncthreads();

        const uint32_t sbase = sb + (c % 3) * 32768;
#pragma unroll
        for (int ks = 0; ks < 4; ks++) {
            uint32_t ah[4][4], bh[2][4];
            const int ar = wm * 64 + (lid & 15);
            const int ag = ks * 2 + (lid >> 4);
#pragma unroll
            for (int im = 0; im < 4; im++)
                ldsm4(ah[im], sbase + OFF_A + SWR(ar + im * 16, ag));
            const int br = wn * 32 + (lid & 7) + ((lid >> 4) & 1) * 8;
            const int bg = ks * 2 + ((lid >> 3) & 1);
#pragma unroll
            for (int g = 0; g < 2; g++)
                ldsm4(bh[g], sbase + OFF_BH + SWR(br + g * 16, bg));
#pragma unroll
            for (int im = 0; im < 4; im++)
#pragma unroll
                for (int in = 0; in < 4; in++)
                    mma_f16(acc[im][in], ah[im], &bh[in >> 1][(in & 1) * 2]);
        }
        // 3-stage ring: no trailing barrier needed
    }

    const int group = lid >> 2, tid4 = lid & 3;

    auto emit = [&](int m, int n, float v) {
        v += bsel[n];
        if (zz == 0) {
            kh[(size_t)m * D_ + n] = __float2half_rn(v);
        } else {
            int bb = m >> 12, kv = m & (LKV_ - 1);
            vth[((size_t)(bb * D_ + n)) * LKV_ + kv] = __float2half_rn(v);
        }
    };

#pragma unroll
    for (int im = 0; im < 4; im++)
#pragma unroll
        for (int in = 0; in < 4; in++) {
            int row = m0 + wm * 64 + im * 16 + group;
            int col = n0 + wn * 32 + in * 8 + tid4 * 2;
            emit(row,     col,     acc[im][in][0]);
            emit(row,     col + 1, acc[im][in][1]);
            emit(row + 8, col,     acc[im][in][2]);
            emit(row + 8, col + 1, acc[im][in][3]);
        }
}

// ---------------------------------------------------------------------------
// Q / O projection: 2-pass fp16, CTA tile 128x64 (-> 256 CTAs), warp 64x16.
// K-chunk 64, 2-stage double buffer. MODE 0: fp32 out (+bias). MODE 1: fp16
// out ((v+bias)*scale).
// ---------------------------------------------------------------------------
#define QO_A   0
#define QO_BH  16384
#define QO_BL  24576
#define QO_STG 32768
#define QO_SMEM 65536

template <int MODE>
__global__ __launch_bounds__(256) void qo_kernel(
    const __half* __restrict__ A,
    const __half* __restrict__ Bh, const __half* __restrict__ Bl,
    float* __restrict__ Cf, __half* __restrict__ Ch,
    const float* __restrict__ bias, float scale)
{
    extern __shared__ char smem[];
    const uint32_t sb = smem_u32(smem);
    const int t = threadIdx.x, wid = t >> 5, lid = t & 31;
    const int wm = wid & 1, wn = wid >> 1;          // wn in 0..3 -> 16-col quarter
    const int m0 = blockIdx.y * 128, n0 = blockIdx.x * 64;

    const __half* Ab  = A  + (size_t)m0 * D_;
    const __half* Bbh = Bh + (size_t)n0 * D_;
    const __half* Bbl = Bl + (size_t)n0 * D_;

    float acc[4][2][4];
#pragma unroll
    for (int i = 0; i < 4; i++)
#pragma unroll
        for (int j = 0; j < 2; j++)
#pragma unroll
            for (int r = 0; r < 4; r++) acc[i][j][r] = 0.f;

    const int nch = D_ >> 6;

    auto load_stage = [&](int c) {
        const int k0 = c << 6;
        const uint32_t sbase = sb + (c & 1) * QO_STG;
#pragma unroll
        for (int i = 0; i < 4; i++) {      // A: 128 rows x 8 granules
            int idx = t + i * 256;
            int r = idx >> 3, s = idx & 7;
            CP_ASYNC16(sbase + QO_A + SWR(r, s), Ab + (size_t)r * D_ + k0 + s * 8);
        }
#pragma unroll
        for (int i = 0; i < 2; i++) {      // B: 64 rows x 8 granules, hi+lo
            int idx = t + i * 256;
            int r = idx >> 3, s = idx & 7;
            size_t ob = (size_t)r * D_ + k0 + s * 8;
            uint32_t so = SWR(r, s);
            CP_ASYNC16(sbase + QO_BH + so, Bbh + ob);
            CP_ASYNC16(sbase + QO_BL + so, Bbl + ob);
        }
        CP_COMMIT();
    };

    load_stage(0);

    for (int c = 0; c < nch; c++) {
        if (c + 1 < nch) { load_stage(c + 1); CP_WAIT(1); }
        else             { CP_WAIT(0); }
        __syncthreads();

        const uint32_t sbase = sb + (c & 1) * QO_STG;
#pragma unroll
        for (int ks = 0; ks < 4; ks++) {
            uint32_t ah[4][4], bh[4], bl[4];
            const int ar = wm * 64 + (lid & 15);
            const int ag = ks * 2 + (lid >> 4);
#pragma unroll
            for (int im = 0; im < 4; im++)
                ldsm4(ah[im], sbase + QO_A + SWR(ar + im * 16, ag));
            const int br = wn * 16 + (lid & 7) + ((lid >> 4) & 1) * 8;
            const int bg = ks * 2 + ((lid >> 3) & 1);
            uint32_t off = SWR(br, bg);
            ldsm4(bh, sbase + QO_BH + off);
            ldsm4(bl, sbase + QO_BL + off);
#pragma unroll
            for (int im = 0; im < 4; im++)
#pragma unroll
                for (int in = 0; in < 2; in++) {
                    mma_f16(acc[im][in], ah[im], &bh[in * 2]);
                    mma_f16(acc[im][in], ah[im], &bl[in * 2]);
                }
        }
        __syncthreads();
    }

    const int group = lid >> 2, tid4 = lid & 3;
#pragma unroll
    for (int im = 0; im < 4; im++)
#pragma unroll
        for (int in = 0; in < 2; in++) {
            int row = m0 + wm * 64 + im * 16 + group;
            int col = n0 + wn * 16 + in * 8 + tid4 * 2;
#pragma unroll
            for (int rr = 0; rr < 2; rr++) {
#pragma unroll
                for (int cc = 0; cc < 2; cc++) {
                    float v = acc[im][in][rr * 2 + cc] + bias[col + cc];
                    if (MODE == 0) {
                        Cf[(size_t)(row + rr * 8) * D_ + col + cc] = v;
                    } else {
                        Ch[(size_t)(row + rr * 8) * D_ + col + cc] = __float2half_rn(v * scale);
                    }
                }
            }
        }
}

// ---------------------------------------------------------------------------
// Flash attention (R11-proven, NO Q-hoist): fp16 single-pass, exp2 softmax,
// Q-tile 64, 128 threads, 3-stage KV ring, single barrier per iteration.
// ---------------------------------------------------------------------------
#define F_Q    0
#define F_ST   16384
#define F_STSZ 32768
#define F_K    0
#define F_V    16384
#define FLASH_SMEM (F_ST + 3 * F_STSZ)   // 114688

__global__ __launch_bounds__(128, 2) void flash_kernel(
    const __half* __restrict__ q, const __half* __restrict__ k,
    const __half* __restrict__ vt, __half* __restrict__ ct)
{
    extern __shared__ char smem[];
    const uint32_t sb = smem_u32(smem);
    const int t = threadIdx.x, wid = t >> 5, lid = t & 31;
    const int z = blockIdx.y, zb = z >> 2, zh = z & 3;
    const int q0 = blockIdx.x * 64;

#pragma unroll
    for (int i = 0; i < 8; i++) {
        int idx = t + i * 128;
        int r = idx >> 4, g = idx & 15;
        const __half* gp = q + ((size_t)(zb * LQ_ + q0 + r)) * D_ + zh * HD_ + g * 8;
        CP_ASYNC16(sb + F_Q + SWQ(r, g), gp);
    }
    CP_COMMIT();

    auto load_kv = [&](int kt2) {
        const int kv0 = kt2 * 64;
        const uint32_t stb = sb + F_ST + (kt2 % 3) * F_STSZ;
#pragma unroll
        for (int i = 0; i < 8; i++) {
            int idx = t + i * 128;
            int r = idx >> 4, g = idx & 15;
            const __half* gp = k + ((size_t)(zb * LKV_ + kv0 + r)) * D_ + zh * HD_ + g * 8;
            CP_ASYNC16(stb + F_K + SWQ(r, g), gp);
        }
#pragma unroll
        for (int i = 0; i < 8; i++) {
            int idx = t + i * 128;
            int r = idx >> 3, g = idx & 7;
            const __half* gp = vt + ((size_t)(zb * D_ + zh * HD_ + r)) * LKV_ + kv0 + g * 8;
            CP_ASYNC16(stb + F_V + SWR(r, g), gp);
        }
        CP_COMMIT();
    };

    load_kv(0);

    float oacc[16][4];
#pragma unroll
    for (int i = 0; i < 16; i++)
#pragma unroll
        for (int j = 0; j < 4; j++) oacc[i][j] = 0.f;
    float mr0 = -1e30f, mr1 = -1e30f, l0 = 0.f, l1 = 0.f;

    for (int kt = 0; kt < LKV_ / 64; kt++) {
        if (kt + 1 < LKV_ / 64) { load_kv(kt + 1); CP_WAIT(1); }
        else                    { CP_WAIT(0); }
        __syncthreads();
        const uint32_t stb = sb + F_ST + (kt % 3) * F_STSZ;

        float sacc[8][4];
#pragma unroll
        for (int i = 0; i < 8; i++)
#pragma unroll
            for (int j = 0; j < 4; j++) sacc[i][j] = 0.f;

#pragma unroll
        for (int ks = 0; ks < 8; ks++) {
            uint32_t aq[4];
            const int ar = wid * 16 + (lid & 15);
            const int ag = ks * 2 + (lid >> 4);
            ldsm4(aq, sb + F_Q + SWQ(ar, ag));
#pragma unroll
            for (int jn = 0; jn < 4; jn++) {
                uint32_t bk4[4];
                const int br = jn * 16 + (lid & 7) + ((lid >> 4) & 1) * 8;
                const int bg = ks * 2 + ((lid >> 3) & 1);
                ldsm4(bk4, stb + F_K + SWQ(br, bg));
                mma_f16(sacc[2 * jn],     aq, &bk4[0]);
                mma_f16(sacc[2 * jn + 1], aq, &bk4[2]);
            }
        }

        float tm0 = -1e30f, tm1 = -1e30f;
#pragma unroll
        for (int i = 0; i < 8; i++) {
            tm0 = fmaxf(tm0, fmaxf(sacc[i][0], sacc[i][1]));
            tm1 = fmaxf(tm1, fmaxf(sacc[i][2], sacc[i][3]));
        }
        tm0 = fmaxf(tm0, __shfl_xor_sync(0xffffffffu, tm0, 1));
        tm0 = fmaxf(tm0, __shfl_xor_sync(0xffffffffu, tm0, 2));
        tm1 = fmaxf(tm1, __shfl_xor_sync(0xffffffffu, tm1, 1));
        tm1 = fmaxf(tm1, __shfl_xor_sync(0xffffffffu, tm1, 2));

        const float mn0 = fmaxf(mr0, tm0), mn1 = fmaxf(mr1, tm1);
        const float al0 = exp2f(mr0 - mn0), al1 = exp2f(mr1 - mn1);
        mr0 = mn0; mr1 = mn1;

        uint32_t phi[8][2];
        float ps0 = 0.f, ps1 = 0.f;
#pragma unroll
        for (int i = 0; i < 8; i++) {
            float p00 = exp2f(sacc[i][0] - mn0);
            float p01 = exp2f(sacc[i][1] - mn0);
            float p10 = exp2f(sacc[i][2] - mn1);
            float p11 = exp2f(sacc[i][3] - mn1);
            ps0 += p00 + p01; ps1 += p10 + p11;
            phi[i][0] = pack_h2(p00, p01);
            phi[i][1] = pack_h2(p10, p11);
        }
        l0 = l0 * al0 + ps0;
        l1 = l1 * al1 + ps1;
        if (al0 != 1.f || al1 != 1.f) {
#pragma unroll
            for (int i = 0; i < 16; i++) {
                oacc[i][0] *= al0; oacc[i][1] *= al0;
                oacc[i][2] *= al1; oacc[i][3] *= al1;
            }
        }

#pragma unroll
        for (int pk = 0; pk < 4; pk++) {
            uint32_t ap[4] = {phi[2 * pk][0], phi[2 * pk][1],
                              phi[2 * pk + 1][0], phi[2 * pk + 1][1]};
#pragma unroll
            for (int jn = 0; jn < 8; jn++) {
                uint32_t bv[4];
                const int vr = jn * 16 + (lid & 7) + ((lid >> 4) & 1) * 8;
                const int vg = pk * 2 + ((lid >> 3) & 1);
                ldsm4(bv, stb + F_V + SWR(vr, vg));
                mma_f16(oacc[2 * jn],     ap, &bv[0]);
                mma_f16(oacc[2 * jn + 1], ap, &bv[2]);
            }
        }
    }

    l0 += __shfl_xor_sync(0xffffffffu, l0, 1);
    l0 += __shfl_xor_sync(0xffffffffu, l0, 2);
    l1 += __shfl_xor_sync(0xffffffffu, l1, 1);
    l1 += __shfl_xor_sync(0xffffffffu, l1, 2);
    const float inv0 = 1.0f / l0, inv1 = 1.0f / l1;

    const int r = lid >> 2, c2 = (lid & 3) * 2;
    const int qg = q0 + wid * 16 + r;
    const size_t row0 = ((size_t)(zb * LQ_) + qg) * D_ + zh * HD_;
    const size_t row1 = row0 + 8 * D_;
#pragma unroll
    for (int jt = 0; jt < 16; jt++) {
        int col = jt * 8 + c2;
        *(uint32_t*)(ct + row0 + col) = pack_h2(oacc[jt][0] * inv0, oacc[jt][1] * inv0);
        *(uint32_t*)(ct + row1 + col) = pack_h2(oacc[jt][2] * inv1, oacc[jt][3] * inv1);
    }
}

// ---------------------------------------------------------------------------
extern "C" void kernel_launch(void* const* d_in, const int* in_sizes, int n_in,
                              void* d_out, int out_size)
{
    const float* x   = (const float*)d_in[0];
    const float* enc = (const float*)d_in[1];
    const float* Wq  = (const float*)d_in[2];
    const float* Wk  = (const float*)d_in[3];
    const float* Wv  = (const float*)d_in[4];
    const float* bq  = (const float*)d_in[5];
    const float* bk  = (const float*)d_in[6];
    const float* bv  = (const float*)d_in[7];
    const float* Wo  = (const float*)d_in[8];
    const float* bo  = (const float*)d_in[9];
    float* out = (float*)d_out;

    __half *xh, *eh, *wqh, *wql, *wk, *wv, *woh, *wol;
    __half *qh, *kh, *vth, *ct;
    cudaGetSymbolAddress((void**)&xh,  g_xh);
    cudaGetSymbolAddress((void**)&eh,  g_eh);
    cudaGetSymbolAddress((void**)&wqh, g_wqhi); cudaGetSymbolAddress((void**)&wql, g_wqlo);
    cudaGetSymbolAddress((void**)&wk,  g_wk);
    cudaGetSymbolAddress((void**)&wv,  g_wv);
    cudaGetSymbolAddress((void**)&woh, g_wohi); cudaGetSymbolAddress((void**)&wol, g_wolo);
    cudaGetSymbolAddress((void**)&qh,  g_qh);   cudaGetSymbolAddress((void**)&kh,  g_kh);
    cudaGetSymbolAddress((void**)&vth, g_vth);  cudaGetSymbolAddress((void**)&ct,  g_ct);

    cudaFuncSetAttribute((const void*)kv_kernel,    cudaFuncAttributeMaxDynamicSharedMemorySize, KV_SMEM);
    cudaFuncSetAttribute((const void*)qo_kernel<0>, cudaFuncAttributeMaxDynamicSharedMemorySize, QO_SMEM);
    cudaFuncSetAttribute((const void*)qo_kernel<1>, cudaFuncAttributeMaxDynamicSharedMemorySize, QO_SMEM);
    cudaFuncSetAttribute((const void*)flash_kernel, cudaFuncAttributeMaxDynamicSharedMemorySize, FLASH_SMEM);

    // 1) single prep launch
    prep_kernel<<<dim3(256, 6), 256>>>(x, enc, Wq, Wk, Wv, Wo,
                                       xh, eh, wqh, wql, wk, wv, woh, wol);

    // 2) Q projection (2-pass, 128x64 tiles -> 256 CTAs, pre-scaled)
    qo_kernel<1><<<dim3(8, 32), 256, QO_SMEM>>>(
        xh, wqh, wql, nullptr, qh, bq, QSCALE_);

    // 3) merged K+V projections (1-pass, z: 0=K, 1=V transposed)
    kv_kernel<<<dim3(4, 128, 2), 256, KV_SMEM>>>(eh, wk, wv, kh, vth, bk, bv);

    // 4) fused flash attention (fp16, exp2) -> ctx fp16
    flash_kernel<<<dim3(LQ_ / 64, B_ * H_), 128, FLASH_SMEM>>>(qh, kh, vth, ct);

    // 5) output projection (2-pass, 128x64 tiles -> 256 CTAs) -> fp32 out
    qo_kernel<0><<<dim3(8, 32), 256, QO_SMEM>>>(
        ct, woh, wol, out, nullptr, bo, 1.0f);
}